// round 3
// baseline (speedup 1.0000x reference)
#include <cuda_runtime.h>
#include <cstddef>

#define F 32
#define P 16

// Flag written by the dtype-detection prepass: 1 if idx/widx are int64, 0 if int32.
__device__ unsigned g_is64;

// jax silently downgrades int64->int32 when x64 is disabled, so the stored dtype
// of idx/widx is environment-dependent. Indices are < 2*M = 400000 < 2^31, so if
// the buffer is int64 every odd 32-bit word (the high half) is exactly 0. Sample
// 64 of them (all within the first n_elems words, safe for either dtype).
// P(false positive | int32) ~ (1/400000)^64 ~ 0. Deterministic per input.
__global__ void detect_dtype_kernel(const unsigned* __restrict__ raw) {
    if (threadIdx.x == 0 && blockIdx.x == 0) {
        unsigned acc = 0u;
        #pragma unroll
        for (int i = 0; i < 64; ++i) acc |= raw[2 * i + 1];
        g_is64 = (acc == 0u) ? 1u : 0u;
    }
}

// One warp per output neuron, one lane per feature column.
// Each pool-row gather is a single coalesced 128B warp load (L2-resident pool).
__global__ __launch_bounds__(256)
void linear_gather_kernel(const float* __restrict__ values0,
                          const float* __restrict__ values1,
                          const float* __restrict__ w_table,
                          const void*  __restrict__ idx_raw,
                          const void*  __restrict__ widx_raw,
                          float* __restrict__ out,
                          int N, int M) {
    const unsigned is64 = g_is64;
    const int gwarp = (blockIdx.x * blockDim.x + threadIdx.x) >> 5;
    const int lane  = threadIdx.x & 31;
    if (gwarp >= N) return;

    // Lanes 0..15 load the neuron's 16 indices (coalesced 128B for int64) and
    // its 16-float weight row (coalesced 64B); broadcast via shuffles below.
    int   my_i = 0;
    float my_w = 0.0f;
    if (lane < P) {
        long long wrow;
        if (is64) {
            my_i = (int)(((const long long*)idx_raw)[(size_t)gwarp * P + lane]);
            wrow = ((const long long*)widx_raw)[gwarp];
        } else {
            my_i = ((const int*)idx_raw)[(size_t)gwarp * P + lane];
            wrow = ((const int*)widx_raw)[gwarp];
        }
        my_w = __ldg(w_table + (size_t)wrow * P + lane);
    }

    float acc = 0.0f;
    #pragma unroll
    for (int p = 0; p < P; ++p) {
        const int   ip = __shfl_sync(0xffffffffu, my_i, p);
        const float wp = __shfl_sync(0xffffffffu, my_w, p);
        const float* src = (ip < M) ? (values0 + (size_t)ip * F)
                                    : (values1 + (size_t)(ip - M) * F);
        acc = fmaf(wp, __ldg(src + lane), acc);
    }
    out[(size_t)gwarp * F + lane] = acc;
}

extern "C" void kernel_launch(void* const* d_in, const int* in_sizes, int n_in,
                              void* d_out, int out_size) {
    // metadata order: values0 [M,F] f32, values1 [M,F] f32, w_table [K,P] f32,
    //                 idx [N,P] int64/int32, widx [N] int64/int32
    const float* values0 = (const float*)d_in[0];
    const float* values1 = (const float*)d_in[1];
    const float* w_table = (const float*)d_in[2];
    const void*  idx     = d_in[3];
    const void*  widx    = d_in[4];
    float* out = (float*)d_out;

    const int M = in_sizes[0] / F;   // rows per source layer
    const int N = in_sizes[4];       // output neurons (widx element count)

    detect_dtype_kernel<<<1, 32>>>((const unsigned*)idx);

    const int threads = 256;                 // 8 warps = 8 neurons per block
    const int warps_per_block = threads / 32;
    const int blocks = (N + warps_per_block - 1) / warps_per_block;
    linear_gather_kernel<<<blocks, threads>>>(values0, values1, w_table,
                                              idx, widx, out, N, M);
}

// round 4
// speedup vs baseline: 2.3715x; 2.3715x over previous
#include <cuda_runtime.h>
#include <cstddef>

#define F 32
#define P 16

// Flag written by the dtype-detection prepass: 1 if idx/widx are int64, 0 if int32.
__device__ unsigned g_is64;

// jax silently downgrades int64->int32 when x64 is disabled, so the stored dtype
// of idx/widx is environment-dependent. Indices are < 2*M = 400000 < 2^31, so if
// the buffer is int64 every odd 32-bit word (the high half) is exactly 0.
// P(false positive | int32 data) ~ (2.5e-6)^64 ~ 0. Deterministic per input.
__global__ void detect_dtype_kernel(const unsigned* __restrict__ raw) {
    if (threadIdx.x == 0 && blockIdx.x == 0) {
        unsigned acc = 0u;
        #pragma unroll
        for (int i = 0; i < 64; ++i) acc |= raw[2 * i + 1];
        g_is64 = (acc == 0u) ? 1u : 0u;
    }
}

// 4 neurons per warp, 8 lanes per neuron, float4 (4 feature columns) per lane.
// Each pool-row gather for the whole warp is ONE LDG.128 (4 rows x 128B).
// idx / w rows are preloaded 2-per-lane and broadcast with width=8 partition
// shuffles whose source lane is a compile-time immediate.
__global__ __launch_bounds__(256)
void linear_gather_kernel(const float* __restrict__ values0,
                          const float* __restrict__ values1,
                          const float* __restrict__ w_table,
                          const void*  __restrict__ idx_raw,
                          const void*  __restrict__ widx_raw,
                          float* __restrict__ out,
                          int N, int M) {
    const unsigned is64 = g_is64;
    const int warp = (blockIdx.x * blockDim.x + threadIdx.x) >> 5;
    const int lane = threadIdx.x & 31;
    const int sub  = lane & 7;        // lane within the neuron's 8-lane group
    const int nb   = warp * 4;
    int n = nb + (lane >> 3);         // this group's neuron
    if (nb >= N) return;
    const bool valid = (n < N);
    if (!valid) n = N - 1;            // clamp for loads; store is predicated

    // ---- preload: 2 indices + 2 weights per lane (16 per 8-lane group) ----
    int ia, ib;                       // idx[n*16 + 2*sub], idx[n*16 + 2*sub+1]
    long long wrow;
    if (is64) {
        const longlong2 L =
            ((const longlong2*)idx_raw)[(size_t)n * (P / 2) + sub];
        ia = (int)L.x; ib = (int)L.y;
        wrow = ((const long long*)widx_raw)[n];
    } else {
        const int2 L = ((const int2*)idx_raw)[(size_t)n * (P / 2) + sub];
        ia = L.x; ib = L.y;
        wrow = ((const int*)widx_raw)[n];
    }
    const float2 w2 =
        ((const float2*)(w_table + (size_t)wrow * P))[sub];  // w[2sub], w[2sub+1]

    // Per-lane feature base pointers (sub*4 columns), values1 pre-shifted by -M rows
    const float* __restrict__ base0 = values0 + sub * 4;
    const float* __restrict__ base1 = values1 + sub * 4 - (size_t)M * F;

    float4 acc = make_float4(0.f, 0.f, 0.f, 0.f);

    #pragma unroll
    for (int p = 0; p < P; ++p) {
        // broadcast within the 8-lane partition; source lane p/2 is an immediate
        const int   ip = (p & 1) ? __shfl_sync(0xffffffffu, ib, p >> 1, 8)
                                 : __shfl_sync(0xffffffffu, ia, p >> 1, 8);
        const float wp = (p & 1) ? __shfl_sync(0xffffffffu, w2.y, p >> 1, 8)
                                 : __shfl_sync(0xffffffffu, w2.x, p >> 1, 8);
        const float* src = (ip < M) ? base0 : base1;
        const float4 v = *(const float4*)(src + (size_t)ip * F);
        acc.x = fmaf(wp, v.x, acc.x);
        acc.y = fmaf(wp, v.y, acc.y);
        acc.z = fmaf(wp, v.z, acc.z);
        acc.w = fmaf(wp, v.w, acc.w);
    }

    if (valid)
        ((float4*)out)[(size_t)n * (F / 4) + sub] = acc;
}

extern "C" void kernel_launch(void* const* d_in, const int* in_sizes, int n_in,
                              void* d_out, int out_size) {
    // metadata order: values0 [M,F] f32, values1 [M,F] f32, w_table [K,P] f32,
    //                 idx [N,P] int64/int32, widx [N] int64/int32
    const float* values0 = (const float*)d_in[0];
    const float* values1 = (const float*)d_in[1];
    const float* w_table = (const float*)d_in[2];
    const void*  idx     = d_in[3];
    const void*  widx    = d_in[4];
    float* out = (float*)d_out;

    const int M = in_sizes[0] / F;   // rows per source layer
    const int N = in_sizes[4];       // output neurons (widx element count)

    detect_dtype_kernel<<<1, 32>>>((const unsigned*)idx);

    const int threads = 256;                       // 8 warps = 32 neurons/block
    const int neurons_per_block = (threads / 32) * 4;
    const int blocks = (N + neurons_per_block - 1) / neurons_per_block;
    linear_gather_kernel<<<blocks, threads>>>(values0, values1, w_table,
                                              idx, widx, out, N, M);
}